// round 13
// baseline (speedup 1.0000x reference)
#include <cuda_runtime.h>
#include <cuda.h>
#include <cstdint>

// Static problem:
//   req_to_token:      [4096, 65536] int32  (single huge input, found by size)
//   req_pool_indices:  [1024] int32 in [0,4096)
//   page_kernel_lens:  [1024] int32 in [1,65536], lens[0]==65536
//   out (float32):     [1024, 1024]
// out[b,p] = float( req_to_token[pool[b], p*64] >> 6 ) if p < ceil(len[b]/64) else 0
//
// R13: exact-ish tail TMA with 128B-aligned chunks. R12 faulted because tail
// sub-boxes < 8 pages put TMA SMEM destinations at non-128B offsets. Now the
// tail is rounded up to a multiple of 8 pages and decomposed over box heights
// {64,32,16,8} largest-first, so every dst offset is a multiple of 128 B.
// Residual overfetch <= 7 pages/row (avg 3.5) vs 31.5 for full boxes.

#define PAGE_SIZE 64
#define MAX_CTX   65536
#define MAX_PAGES 1024
#define BATCH     1024
#define POOL      4096

#define BOX_PAGES 64
#define NBOX      (MAX_PAGES / BOX_PAGES)   // 16
#define BOX_BYTES (BOX_PAGES * 16)          // 1024 B (16 B per page)
#define SLOTS     (NBOX / 2)                // 8 boxes per parity block
#define THREADS   128
#define NMAPS     4                          // box heights 64,32,16,8

struct TMaps { CUtensorMap m[NMAPS]; };

__device__ __forceinline__ uint32_t smem_u32(const void* p) {
    return (uint32_t)__cvta_generic_to_shared(p);
}

__device__ __forceinline__ void tma_box(const CUtensorMap* tm, uint32_t dst,
                                        int page_y, int pool, uint32_t mbar) {
    asm volatile(
        "cp.async.bulk.tensor.3d.shared::cta.global.tile.mbarrier::complete_tx::bytes "
        "[%0], [%1, {%2, %3, %4}], [%5];"
        :: "r"(dst), "l"(tm), "r"(0), "r"(page_y), "r"(pool), "r"(mbar)
        : "memory");
}

// ---------------- parity-split aligned-tail TMA kernel ----------------
__global__ __launch_bounds__(THREADS)
void kv_par_kernel(const __grid_constant__ TMaps tmaps,
                   const int* __restrict__ small0,
                   const int* __restrict__ small1,
                   float* __restrict__ out)
{
    __shared__ alignas(128) int4 s_pg[SLOTS * BOX_PAGES];  // 8 KB
    __shared__ alignas(8) uint64_t s_mbar;

    const bool s0_is_lens = (__ldg(&small0[0]) > 4095);
    const int* __restrict__ pools = s0_is_lens ? small1 : small0;
    const int* __restrict__ lens  = s0_is_lens ? small0 : small1;

    const int r   = blockIdx.x & (BATCH - 1);   // row
    const int par = blockIdx.x >> 10;           // 0 = even boxes, 1 = odd boxes

    const int pool = __ldg(&pools[r]) & (POOL - 1);
    const int len  = __ldg(&lens[r]);
    int num_pages  = (len + PAGE_SIZE - 1) >> 6;
    if (num_pages < 1)         num_pages = 1;
    if (num_pages > MAX_PAGES) num_pages = MAX_PAGES;

    const int nbox_full = num_pages >> 6;             // complete boxes 0..16
    const int rem       = num_pages & 63;             // ragged pages 0..63
    const int nbox      = nbox_full + (rem ? 1 : 0);  // total live boxes 1..16

    // Live slots for this parity (wait/epilogue bound), as in R11.
    int L = (nbox - par + 1) >> 1;
    if (L < 0) L = 0;
    if (L > SLOTS) L = SLOTS;

    // Full boxes owned by this parity; ragged box owned iff its parity matches.
    int nfull_own = (nbox_full - par + 1) >> 1;
    if (nfull_own < 0) nfull_own = 0;
    const bool rag_own = (rem > 0) && ((nbox_full & 1) == par);
    const int  rem8    = (rem + 7) & ~7;               // 8..64, 128B-aligned chunks

    const uint32_t xbytes = (uint32_t)(nfull_own * BOX_BYTES)
                          + (rag_own ? (uint32_t)(rem8 * 16) : 0u);

    const uint32_t mbar = smem_u32(&s_mbar);

    if (threadIdx.x == 0 && xbytes > 0) {
        asm volatile("mbarrier.init.shared.b64 [%0], 1;" :: "r"(mbar) : "memory");
        asm volatile("fence.proxy.async.shared::cta;" ::: "memory");
        asm volatile("mbarrier.arrive.expect_tx.shared.b64 _, [%0], %1;"
                     :: "r"(mbar), "r"(xbytes) : "memory");
        const uint32_t dst0 = smem_u32(&s_pg[0]);

        // Full boxes: slot s holds box par+2s.
        #pragma unroll 1
        for (int s = 0; s < nfull_own; s++) {
            tma_box(&tmaps.m[0], dst0 + s * (uint32_t)BOX_BYTES,
                    (par + 2 * s) * BOX_PAGES, pool, mbar);
        }
        // Ragged box: binary decomposition over {64,32,16,8}, largest first.
        // off stays a multiple of 8 -> dst offset multiple of 128 B.
        if (rag_own) {
            const int s_r  = (nbox_full - par) >> 1;          // its slot
            const int base = nbox_full * BOX_PAGES;           // first page
            const uint32_t dst = dst0 + s_r * (uint32_t)BOX_BYTES;
            int off = 0;
            #pragma unroll
            for (int k = 0; k < NMAPS; k++) {                 // 64,32,16,8
                const int sz = BOX_PAGES >> k;
                if (rem8 & sz) {
                    tma_box(&tmaps.m[k], dst + (uint32_t)(off * 16),
                            base + off, pool, mbar);
                    off += sz;
                }
            }
        }
    }
    __syncthreads();

    if (xbytes > 0) {
        uint32_t done;
        asm volatile(
            "{\n\t.reg .pred p;\n\t"
            "mbarrier.try_wait.parity.acquire.cta.shared::cta.b64 p, [%1], 0;\n\t"
            "selp.b32 %0, 1, 0, p;\n\t}"
            : "=r"(done) : "r"(mbar) : "memory");
        if (!done) {
            asm volatile(
                "{\n\t.reg .pred P1;\n\t"
                "WL_%=:\n\t"
                "mbarrier.try_wait.parity.acquire.cta.shared::cta.b64 P1, [%0], 0, 0x989680;\n\t"
                "@P1 bra.uni WD_%=;\n\t"
                "bra.uni WL_%=;\n\t"
                "WD_%=:\n\t}"
                :: "r"(mbar) : "memory");
        }
    }

    // Epilogue: 8 slots x 64 pages; 128 threads, 2 slots per iteration.
    float* __restrict__ orow = out + (long long)r * MAX_PAGES;
    const int half = threadIdx.x >> 6;          // 0/1
    const int pg   = threadIdx.x & 63;
    #pragma unroll
    for (int i = 0; i < SLOTS / 2; i++) {
        const int s    = i * 2 + half;          // slot 0..7
        const int boxi = par + 2 * s;
        const int p    = boxi * BOX_PAGES + pg;
        float v = 0.0f;
        if (s < L && p < num_pages)
            v = (float)(s_pg[s * BOX_PAGES + pg].x >> 6);
        orow[p] = v;
    }
}

// ---------------- fallback: proven LDG kernel ----------------
__global__ __launch_bounds__(256)
void kv_ldg_kernel(const int* __restrict__ req_to_token,
                   const int* __restrict__ small0,
                   const int* __restrict__ small1,
                   float* __restrict__ out)
{
    const bool s0_is_lens = (__ldg(&small0[0]) > 4095);
    const int* __restrict__ pools = s0_is_lens ? small1 : small0;
    const int* __restrict__ lens  = s0_is_lens ? small0 : small1;

    const int b    = blockIdx.x;
    const int pool = __ldg(&pools[b]) & (POOL - 1);
    const int len  = __ldg(&lens[b]);
    int num_pages  = (len + PAGE_SIZE - 1) >> 6;
    if (num_pages < 0)         num_pages = 0;
    if (num_pages > MAX_PAGES) num_pages = MAX_PAGES;

    const int* __restrict__ row =
        req_to_token + (long long)pool * (long long)MAX_CTX;
    const int p0 = threadIdx.x << 2;

    float4 v;
    v.x = (p0 + 0 < num_pages) ? (float)(__ldg(&row[(p0 + 0) * PAGE_SIZE]) >> 6) : 0.0f;
    v.y = (p0 + 1 < num_pages) ? (float)(__ldg(&row[(p0 + 1) * PAGE_SIZE]) >> 6) : 0.0f;
    v.z = (p0 + 2 < num_pages) ? (float)(__ldg(&row[(p0 + 2) * PAGE_SIZE]) >> 6) : 0.0f;
    v.w = (p0 + 3 < num_pages) ? (float)(__ldg(&row[(p0 + 3) * PAGE_SIZE]) >> 6) : 0.0f;

    *reinterpret_cast<float4*>(out + (long long)b * MAX_PAGES + p0) = v;
}

// ---------------- host ----------------
typedef CUresult (*EncodeTiledFn)(
    CUtensorMap*, CUtensorMapDataType, cuuint32_t, void*,
    const cuuint64_t*, const cuuint64_t*, const cuuint32_t*, const cuuint32_t*,
    CUtensorMapInterleave, CUtensorMapSwizzle, CUtensorMapL2promotion,
    CUtensorMapFloatOOBfill);

extern "C" void kernel_launch(void* const* d_in, const int* in_sizes, int n_in,
                              void* d_out, int out_size)
{
    int big_i = 0;
    for (int i = 1; i < n_in; i++)
        if (in_sizes[i] > in_sizes[big_i]) big_i = i;

    const int* big = (const int*)d_in[big_i];
    const int* small_arr[2] = {big, big};
    int ns = 0;
    for (int i = 0; i < n_in && ns < 2; i++)
        if (i != big_i) small_arr[ns++] = (const int*)d_in[i];

    static TMaps s_tmaps;
    static const void* s_tmap_for = nullptr;
    static bool s_tma_ok = false;

    if (s_tmap_for != (const void*)big) {
        s_tmap_for = (const void*)big;
        s_tma_ok = false;

        EncodeTiledFn encode = nullptr;
        cudaDriverEntryPointQueryResult qr;
        if (cudaGetDriverEntryPointByVersion("cuTensorMapEncodeTiled",
                                             (void**)&encode, 12000,
                                             cudaEnableDefault, &qr) == cudaSuccess
            && encode != nullptr) {
            cuuint64_t dims[3]    = {64, MAX_PAGES, POOL};
            cuuint64_t strides[2] = {PAGE_SIZE * 4ull,
                                     (cuuint64_t)MAX_CTX * 4ull};
            cuuint32_t estr[3]    = {1, 1, 1};
            bool ok = true;
            for (int k = 0; k < NMAPS; k++) {                 // 64,32,16,8
                cuuint32_t box[3] = {4, (cuuint32_t)(BOX_PAGES >> k), 1};
                CUresult r = encode(&s_tmaps.m[k], CU_TENSOR_MAP_DATA_TYPE_INT32,
                                    3, (void*)big, dims, strides, box, estr,
                                    CU_TENSOR_MAP_INTERLEAVE_NONE,
                                    CU_TENSOR_MAP_SWIZZLE_NONE,
                                    CU_TENSOR_MAP_L2_PROMOTION_NONE,
                                    CU_TENSOR_MAP_FLOAT_OOB_FILL_NONE);
                if (r != CUDA_SUCCESS) { ok = false; break; }
            }
            s_tma_ok = ok;
        }
    }

    if (s_tma_ok) {
        kv_par_kernel<<<2 * BATCH, THREADS>>>(s_tmaps, small_arr[0],
                                              small_arr[1], (float*)d_out);
    } else {
        kv_ldg_kernel<<<BATCH, 256>>>(big, small_arr[0], small_arr[1],
                                      (float*)d_out);
    }
}